// round 2
// baseline (speedup 1.0000x reference)
#include <cuda_runtime.h>

// MultiHeadAttention: B=2, S=2048, D=1024, H=16, dk=64
// Round 2: fp32 SIMT baseline resubmit (R1 was a container/infra failure).

#define DM   1024
#define NH   16
#define DKH  64
#define BB   2
#define SS   2048
#define MR   (BB*SS)     // 4096 rows

// Scratch (allocation-free requirement): 64 MB of __device__ globals.
__device__ float g_Q[BB*NH*SS*DKH];
__device__ float g_K[BB*NH*SS*DKH];
__device__ float g_V[BB*NH*SS*DKH];
__device__ float g_Y[BB*SS*DM];

// ---------------------------------------------------------------------------
// 128x128 tile GEMM body: C[row0+.. , col0+..] = A[M,K] * B[N,K]^T  (NT GEMM)
// A row-major stride DM, B row-major stride DM. 256 threads, 8x8 per thread.
// ---------------------------------------------------------------------------
__device__ __forceinline__ void gemm128x128(
    const float* __restrict__ A, const float* __restrict__ Bw,
    int row0, int col0, float (&c)[8][8])
{
    __shared__ float As[8][128];
    __shared__ float Bs[8][128];

    const int tid = threadIdx.x;
    const int tx  = tid & 15;
    const int ty  = tid >> 4;
    const int lr  = tid >> 1;          // 0..127
    const int lc  = (tid & 1) << 2;    // 0 or 4

    const float* aPtr = A  + (size_t)(row0 + lr) * DM + lc;
    const float* bPtr = Bw + (size_t)(col0 + lr) * DM + lc;

    for (int k0 = 0; k0 < DM; k0 += 8) {
        float4 av = *(const float4*)(aPtr + k0);
        float4 bv = *(const float4*)(bPtr + k0);
        __syncthreads();               // previous-iter consumers done
        As[lc+0][lr] = av.x; As[lc+1][lr] = av.y;
        As[lc+2][lr] = av.z; As[lc+3][lr] = av.w;
        Bs[lc+0][lr] = bv.x; Bs[lc+1][lr] = bv.y;
        Bs[lc+2][lr] = bv.z; Bs[lc+3][lr] = bv.w;
        __syncthreads();               // tiles visible
        #pragma unroll
        for (int kk = 0; kk < 8; kk++) {
            float4 a0 = *(const float4*)&As[kk][ty*4];
            float4 a1 = *(const float4*)&As[kk][ty*4+64];
            float4 b0 = *(const float4*)&Bs[kk][tx*4];
            float4 b1 = *(const float4*)&Bs[kk][tx*4+64];
            float ar[8] = {a0.x,a0.y,a0.z,a0.w,a1.x,a1.y,a1.z,a1.w};
            float br[8] = {b0.x,b0.y,b0.z,b0.w,b1.x,b1.y,b1.z,b1.w};
            #pragma unroll
            for (int i = 0; i < 8; i++)
                #pragma unroll
                for (int j = 0; j < 8; j++)
                    c[i][j] += ar[i] * br[j];
        }
    }
}

// ---------------------------------------------------------------------------
// QKV projection: z = {0:Q, 1:K, 2:V}. Writes head-split layout [b,h,s,d].
// ---------------------------------------------------------------------------
__global__ __launch_bounds__(256) void qkv_kernel(
    const float* __restrict__ x,
    const float* __restrict__ Wq,
    const float* __restrict__ Wk,
    const float* __restrict__ Wv)
{
    const float* W   = (blockIdx.z == 0) ? Wq : (blockIdx.z == 1) ? Wk : Wv;
    float*       Out = (blockIdx.z == 0) ? g_Q : (blockIdx.z == 1) ? g_K : g_V;

    float c[8][8];
    #pragma unroll
    for (int i = 0; i < 8; i++)
        #pragma unroll
        for (int j = 0; j < 8; j++) c[i][j] = 0.f;

    const int row0 = blockIdx.y * 128;
    const int col0 = blockIdx.x * 128;
    gemm128x128(x, W, row0, col0, c);

    const int tx = threadIdx.x & 15;
    const int ty = threadIdx.x >> 4;

    #pragma unroll
    for (int ib = 0; ib < 2; ib++) {
        #pragma unroll
        for (int ii = 0; ii < 4; ii++) {
            const int r = row0 + ib*64 + ty*4 + ii;
            const int b = r >> 11;          // r / 2048
            const int s = r & 2047;
            #pragma unroll
            for (int jb = 0; jb < 2; jb++) {
                const int n = col0 + jb*64 + tx*4;
                const int h = n >> 6;
                const int d = n & 63;
                float4 v = make_float4(c[ib*4+ii][jb*4+0], c[ib*4+ii][jb*4+1],
                                       c[ib*4+ii][jb*4+2], c[ib*4+ii][jb*4+3]);
                *(float4*)&Out[(((size_t)(b*NH + h))*SS + s)*DKH + d] = v;
            }
        }
    }
}

// ---------------------------------------------------------------------------
// Output projection: out = Y @ Wo^T, plain [B,S,D] layout.
// ---------------------------------------------------------------------------
__global__ __launch_bounds__(256) void outproj_kernel(
    const float* __restrict__ Wo, float* __restrict__ out)
{
    float c[8][8];
    #pragma unroll
    for (int i = 0; i < 8; i++)
        #pragma unroll
        for (int j = 0; j < 8; j++) c[i][j] = 0.f;

    const int row0 = blockIdx.y * 128;
    const int col0 = blockIdx.x * 128;
    gemm128x128(g_Y, Wo, row0, col0, c);

    const int tx = threadIdx.x & 15;
    const int ty = threadIdx.x >> 4;

    #pragma unroll
    for (int ib = 0; ib < 2; ib++) {
        #pragma unroll
        for (int ii = 0; ii < 4; ii++) {
            const int r = row0 + ib*64 + ty*4 + ii;
            #pragma unroll
            for (int jb = 0; jb < 2; jb++) {
                const int n = col0 + jb*64 + tx*4;
                float4 v = make_float4(c[ib*4+ii][jb*4+0], c[ib*4+ii][jb*4+1],
                                       c[ib*4+ii][jb*4+2], c[ib*4+ii][jb*4+3]);
                *(float4*)&out[(size_t)r * DM + n] = v;
            }
        }
    }
}

// ---------------------------------------------------------------------------
// Flash attention: block = (b, h, 64-query tile), 32-key tiles, online softmax.
// smem: Qs 17408 + Ks 8704 + Vs 8704 + Ps 9216 + msk 128 = 44160 B (< 48K).
// Thread map (ty 0..15, tx 0..15):
//   QK:  q = ty+16i (i<4),  k = tx+16j (j<2)
//   PV/O: q = ty+16i,       d = tx*4 + jj (jj<4)
// ---------------------------------------------------------------------------
__global__ __launch_bounds__(256) void attn_kernel(const int* __restrict__ mask)
{
    __shared__ float Qs[64][68];
    __shared__ float Ks[32][68];
    __shared__ float Vs[32][68];
    __shared__ float Ps[64][36];
    __shared__ int   msk[32];

    const int b  = blockIdx.z;
    const int h  = blockIdx.y;
    const int q0 = blockIdx.x * 64;

    const size_t base = (size_t)(b*NH + h) * SS * DKH;
    const float* Qp = g_Q + base;
    const float* Kp = g_K + base;
    const float* Vp = g_V + base;

    const int tid = threadIdx.x;
    const int tx  = tid & 15;
    const int ty  = tid >> 4;

    // Load Q tile (64x64): 16 floats per thread
    #pragma unroll
    for (int v = 0; v < 4; v++) {
        const int idx = tid + v*256;
        const int r   = idx >> 4;
        const int c4  = (idx & 15) << 2;
        *(float4*)&Qs[r][c4] = *(const float4*)&Qp[(size_t)(q0 + r)*DKH + c4];
    }

    float O[4][4];
    float m[4], l[4];
    #pragma unroll
    for (int i = 0; i < 4; i++) {
        m[i] = -1e30f; l[i] = 0.f;
        O[i][0] = O[i][1] = O[i][2] = O[i][3] = 0.f;
    }

    for (int kt = 0; kt < SS; kt += 32) {
        __syncthreads();   // previous PV done before overwriting Ks/Vs
        #pragma unroll
        for (int v = 0; v < 2; v++) {
            const int idx = tid + v*256;
            const int r   = idx >> 4;
            const int c4  = (idx & 15) << 2;
            *(float4*)&Ks[r][c4] = *(const float4*)&Kp[(size_t)(kt + r)*DKH + c4];
            *(float4*)&Vs[r][c4] = *(const float4*)&Vp[(size_t)(kt + r)*DKH + c4];
        }
        if (tid < 32) msk[tid] = mask[b*SS + kt + tid];
        __syncthreads();

        // --- scores: s[i][j] = Q[ty+16i] . K[tx+16j] ---
        float sv[4][2];
        #pragma unroll
        for (int i = 0; i < 4; i++) { sv[i][0] = 0.f; sv[i][1] = 0.f; }

        #pragma unroll
        for (int d4 = 0; d4 < 64; d4 += 4) {
            float4 k0v = *(const float4*)&Ks[tx][d4];
            float4 k1v = *(const float4*)&Ks[tx+16][d4];
            #pragma unroll
            for (int i = 0; i < 4; i++) {
                float4 qv = *(const float4*)&Qs[ty + 16*i][d4];
                sv[i][0] += qv.x*k0v.x + qv.y*k0v.y + qv.z*k0v.z + qv.w*k0v.w;
                sv[i][1] += qv.x*k1v.x + qv.y*k1v.y + qv.z*k1v.z + qv.w*k1v.w;
            }
        }
        __syncthreads();   // previous Ps epoch fully consumed before rewrite

        // --- online softmax update ---
        const int kk0 = tx, kk1 = tx + 16;
        const int m0v = msk[kk0], m1v = msk[kk1];
        #pragma unroll
        for (int i = 0; i < 4; i++) {
            float s0 = sv[i][0] * 0.125f;
            float s1 = sv[i][1] * 0.125f;
            if (m0v == 0) s0 = -1e30f;
            if (m1v == 0) s1 = -1e30f;
            float tm = fmaxf(s0, s1);
            #pragma unroll
            for (int o = 8; o; o >>= 1)
                tm = fmaxf(tm, __shfl_xor_sync(0xffffffffu, tm, o));
            const float mn  = fmaxf(m[i], tm);
            const float fac = (m[i] < -1e29f) ? 0.f : __expf(m[i] - mn);
            const float p0  = (s0 < -1e29f) ? 0.f : __expf(s0 - mn);
            const float p1  = (s1 < -1e29f) ? 0.f : __expf(s1 - mn);
            float rs = p0 + p1;
            #pragma unroll
            for (int o = 8; o; o >>= 1)
                rs += __shfl_xor_sync(0xffffffffu, rs, o);
            l[i] = l[i]*fac + rs;
            m[i] = mn;
            O[i][0] *= fac; O[i][1] *= fac; O[i][2] *= fac; O[i][3] *= fac;
            Ps[ty + 16*i][kk0] = p0;
            Ps[ty + 16*i][kk1] = p1;
        }
        __syncthreads();

        // --- PV: O[q][tx*4 + jj] += sum_k P[q][k] * V[k][tx*4 + jj] ---
        #pragma unroll 4
        for (int k = 0; k < 32; k++) {
            float4 vv = *(const float4*)&Vs[k][tx*4];
            #pragma unroll
            for (int i = 0; i < 4; i++) {
                const float p = Ps[ty + 16*i][k];
                O[i][0] += p * vv.x;
                O[i][1] += p * vv.y;
                O[i][2] += p * vv.z;
                O[i][3] += p * vv.w;
            }
        }
    }

    // --- normalize + write context into Y[b, s, h*64 + d] ---
    #pragma unroll
    for (int i = 0; i < 4; i++) {
        const int q   = q0 + ty + 16*i;
        const float inv = (l[i] > 0.f) ? (1.0f / l[i]) : 0.f;
        float4 ov = make_float4(O[i][0]*inv, O[i][1]*inv, O[i][2]*inv, O[i][3]*inv);
        *(float4*)&g_Y[((size_t)b*SS + q)*DM + h*DKH + tx*4] = ov;
    }
}

// ---------------------------------------------------------------------------
extern "C" void kernel_launch(void* const* d_in, const int* in_sizes, int n_in,
                              void* d_out, int out_size)
{
    const float* x    = (const float*)d_in[0];
    const int*   mask = (const int*)  d_in[1];
    const float* Wq   = (const float*)d_in[2];
    const float* Wk   = (const float*)d_in[3];
    const float* Wv   = (const float*)d_in[4];
    const float* Wo   = (const float*)d_in[5];
    float*       out  = (float*)d_out;

    // 1) QKV projections (fused, z-indexed)
    qkv_kernel<<<dim3(DM/128, MR/128, 3), 256>>>(x, Wq, Wk, Wv);
    // 2) Flash attention
    attn_kernel<<<dim3(SS/64, NH, BB), 256>>>(mask);
    // 3) Output projection
    outproj_kernel<<<dim3(DM/128, MR/128, 1), 256>>>(Wo, out);
}

// round 6
// speedup vs baseline: 1.3163x; 1.3163x over previous
#include <cuda_runtime.h>
#include <cstdint>

// MultiHeadAttention: B=2, S=2048, D=1024, H=16, dk=64
// Round 6: harness targets compute_100 (NOT sm_100a) => no tcgen05.
//          Projections via portable mma.sync tf32 (m16n8k8). Attention = R2 SIMT.

#define DM   1024
#define NH   16
#define DKH  64
#define BB   2
#define SS   2048
#define MR   (BB*SS)     // 4096 rows

__device__ float g_Q[BB*NH*SS*DKH];
__device__ float g_K[BB*NH*SS*DKH];
__device__ float g_V[BB*NH*SS*DKH];
__device__ float g_Y[BB*SS*DM];

// ---------------------------------------------------------------------------
// mma.sync tf32 helpers (portable PTX, sm_80+)
// ---------------------------------------------------------------------------
__device__ __forceinline__ uint32_t f2tf32(float f) {
    uint32_t u;
    asm("cvt.rna.tf32.f32 %0, %1;" : "=r"(u) : "f"(f));
    return u;
}
__device__ __forceinline__ void mma_16x8x8(float* c, const uint32_t* a, const uint32_t* b) {
    asm volatile(
        "mma.sync.aligned.m16n8k8.row.col.f32.tf32.tf32.f32 "
        "{%0,%1,%2,%3}, {%4,%5,%6,%7}, {%8,%9}, {%0,%1,%2,%3};"
        : "+f"(c[0]), "+f"(c[1]), "+f"(c[2]), "+f"(c[3])
        : "r"(a[0]), "r"(a[1]), "r"(a[2]), "r"(a[3]), "r"(b[0]), "r"(b[1]));
}

// ---------------------------------------------------------------------------
// tf32 tensor-core GEMM body: C[128,128] = A[M,K] * Bw[N,K]^T  (both row-major,
// stride DM). 256 threads = 8 warps (2 row x 4 col), warp tile 64x32.
// KC=16, double-buffered smem, pad to stride 20 (conflict-free).
// Result left in c[4][4][4] fragments.
// ---------------------------------------------------------------------------
#define KC     16
#define LDT    20   // padded row stride (floats)

__device__ __forceinline__ void mma_gemm_body(
    const float* __restrict__ A, const float* __restrict__ Bw,
    int row0, int col0, float (&c)[4][4][4],
    uint32_t (*As)[LDT], uint32_t (*Bs)[LDT])   // [2*128][LDT] each
{
    const int tid  = threadIdx.x;
    const int wid  = tid >> 5;
    const int lane = tid & 31;
    const int g    = lane >> 2;      // group id 0..7
    const int t    = lane & 3;       // thread-in-group 0..3
    const int wRow = (wid >> 2) * 64;   // 0 or 64
    const int wCol = (wid & 3) * 32;    // 0,32,64,96

    // load map: f = tid + i*256 (i<2); row = f>>2; col = (f&3)*4
    const int lrow  = tid >> 2;              // base row for i=0 (0..63); i=1 adds 64
    const int lcol  = (tid & 3) << 2;        // 0,4,8,12
    const float* aPtr = A  + (size_t)(row0 + lrow) * DM + lcol;
    const float* bPtr = Bw + (size_t)(col0 + lrow) * DM + lcol;

    float4 av[2], bv[2];

    // prologue: chunk 0 -> buf 0
    #pragma unroll
    for (int i = 0; i < 2; i++) {
        av[i] = *(const float4*)(aPtr + (size_t)i*64*DM);
        bv[i] = *(const float4*)(bPtr + (size_t)i*64*DM);
    }
    #pragma unroll
    for (int i = 0; i < 2; i++) {
        uint32_t* as = &As[0*128 + lrow + i*64][lcol];
        uint32_t* bs = &Bs[0*128 + lrow + i*64][lcol];
        as[0]=f2tf32(av[i].x); as[1]=f2tf32(av[i].y); as[2]=f2tf32(av[i].z); as[3]=f2tf32(av[i].w);
        bs[0]=f2tf32(bv[i].x); bs[1]=f2tf32(bv[i].y); bs[2]=f2tf32(bv[i].z); bs[3]=f2tf32(bv[i].w);
    }
    __syncthreads();

    const int NCHUNK = DM / KC;   // 64
    for (int ch = 0; ch < NCHUNK; ++ch) {
        const int buf = (ch & 1) * 128;

        // issue global loads for next chunk (latency overlapped with mma)
        if (ch < NCHUNK-1) {
            const int k0 = (ch+1) * KC;
            #pragma unroll
            for (int i = 0; i < 2; i++) {
                av[i] = *(const float4*)(aPtr + (size_t)i*64*DM + k0);
                bv[i] = *(const float4*)(bPtr + (size_t)i*64*DM + k0);
            }
        }

        // compute: 2 k-steps of m16n8k8
        #pragma unroll
        for (int ks = 0; ks < 2; ks++) {
            const int kb = ks * 8;
            uint32_t af[4][4], bf[4][2];
            #pragma unroll
            for (int i = 0; i < 4; i++) {
                const int r = wRow + i*16 + g;
                af[i][0] = As[buf + r    ][kb + t];
                af[i][1] = As[buf + r + 8][kb + t];
                af[i][2] = As[buf + r    ][kb + t + 4];
                af[i][3] = As[buf + r + 8][kb + t + 4];
            }
            #pragma unroll
            for (int j = 0; j < 4; j++) {
                const int n = wCol + j*8 + g;
                bf[j][0] = Bs[buf + n][kb + t];
                bf[j][1] = Bs[buf + n][kb + t + 4];
            }
            #pragma unroll
            for (int i = 0; i < 4; i++)
                #pragma unroll
                for (int j = 0; j < 4; j++)
                    mma_16x8x8(c[i][j], af[i], bf[j]);
        }

        __syncthreads();   // all warps done reading buf; buf^1 consumers done
        if (ch < NCHUNK-1) {
            const int nb = ((ch+1) & 1) * 128;
            #pragma unroll
            for (int i = 0; i < 2; i++) {
                uint32_t* as = &As[nb + lrow + i*64][lcol];
                uint32_t* bs = &Bs[nb + lrow + i*64][lcol];
                as[0]=f2tf32(av[i].x); as[1]=f2tf32(av[i].y); as[2]=f2tf32(av[i].z); as[3]=f2tf32(av[i].w);
                bs[0]=f2tf32(bv[i].x); bs[1]=f2tf32(bv[i].y); bs[2]=f2tf32(bv[i].z); bs[3]=f2tf32(bv[i].w);
            }
            __syncthreads();
        }
    }
}

// ---------------------------------------------------------------------------
// QKV projection. grid = (8, 32, 3); block = 256. Writes [b,h,s,d] layout.
// ---------------------------------------------------------------------------
__global__ __launch_bounds__(256) void qkv_mma(
    const float* __restrict__ x,
    const float* __restrict__ Wq,
    const float* __restrict__ Wk,
    const float* __restrict__ Wv)
{
    __shared__ uint32_t As[2*128][LDT];
    __shared__ uint32_t Bs[2*128][LDT];

    const float* W   = (blockIdx.z == 0) ? Wq : (blockIdx.z == 1) ? Wk : Wv;
    float*       Out = (blockIdx.z == 0) ? g_Q : (blockIdx.z == 1) ? g_K : g_V;

    float c[4][4][4];
    #pragma unroll
    for (int i = 0; i < 4; i++)
        #pragma unroll
        for (int j = 0; j < 4; j++)
            c[i][j][0]=c[i][j][1]=c[i][j][2]=c[i][j][3]=0.f;

    const int row0 = blockIdx.y * 128;
    const int col0 = blockIdx.x * 128;
    mma_gemm_body(x, W, row0, col0, c, As, Bs);

    const int tid  = threadIdx.x;
    const int wid  = tid >> 5;
    const int lane = tid & 31;
    const int g    = lane >> 2;
    const int t    = lane & 3;
    const int wRow = (wid >> 2) * 64;
    const int wCol = (wid & 3) * 32;

    #pragma unroll
    for (int i = 0; i < 4; i++) {
        #pragma unroll
        for (int j = 0; j < 4; j++) {
            const int n  = col0 + wCol + j*8 + 2*t;
            const int h  = n >> 6;
            const int d  = n & 63;
            const int r0 = row0 + wRow + i*16 + g;
            const int r1 = r0 + 8;
            {
                const int b = r0 >> 11, s = r0 & 2047;
                *(float2*)&Out[(((size_t)(b*NH + h))*SS + s)*DKH + d] =
                    make_float2(c[i][j][0], c[i][j][1]);
            }
            {
                const int b = r1 >> 11, s = r1 & 2047;
                *(float2*)&Out[(((size_t)(b*NH + h))*SS + s)*DKH + d] =
                    make_float2(c[i][j][2], c[i][j][3]);
            }
        }
    }
}

// ---------------------------------------------------------------------------
// Output projection. grid = (8, 32); block = 256. Plain [r, n] output.
// ---------------------------------------------------------------------------
__global__ __launch_bounds__(256) void outproj_mma(
    const float* __restrict__ Wo, float* __restrict__ out)
{
    __shared__ uint32_t As[2*128][LDT];
    __shared__ uint32_t Bs[2*128][LDT];

    float c[4][4][4];
    #pragma unroll
    for (int i = 0; i < 4; i++)
        #pragma unroll
        for (int j = 0; j < 4; j++)
            c[i][j][0]=c[i][j][1]=c[i][j][2]=c[i][j][3]=0.f;

    const int row0 = blockIdx.y * 128;
    const int col0 = blockIdx.x * 128;
    mma_gemm_body(g_Y, Wo, row0, col0, c, As, Bs);

    const int tid  = threadIdx.x;
    const int wid  = tid >> 5;
    const int lane = tid & 31;
    const int g    = lane >> 2;
    const int t    = lane & 3;
    const int wRow = (wid >> 2) * 64;
    const int wCol = (wid & 3) * 32;

    #pragma unroll
    for (int i = 0; i < 4; i++) {
        #pragma unroll
        for (int j = 0; j < 4; j++) {
            const int n  = col0 + wCol + j*8 + 2*t;
            const int r0 = row0 + wRow + i*16 + g;
            *(float2*)&out[(size_t)r0 * DM + n]     = make_float2(c[i][j][0], c[i][j][1]);
            *(float2*)&out[(size_t)(r0+8) * DM + n] = make_float2(c[i][j][2], c[i][j][3]);
        }
    }
}

// ---------------------------------------------------------------------------
// Flash attention (unchanged from passing R2 baseline).
// ---------------------------------------------------------------------------
__global__ __launch_bounds__(256) void attn_kernel(const int* __restrict__ mask)
{
    __shared__ float Qs[64][68];
    __shared__ float Ks[32][68];
    __shared__ float Vs[32][68];
    __shared__ float Ps[64][36];
    __shared__ int   msk[32];

    const int b  = blockIdx.z;
    const int h  = blockIdx.y;
    const int q0 = blockIdx.x * 64;

    const size_t base = (size_t)(b*NH + h) * SS * DKH;
    const float* Qp = g_Q + base;
    const float* Kp = g_K + base;
    const float* Vp = g_V + base;

    const int tid = threadIdx.x;
    const int tx  = tid & 15;
    const int ty  = tid >> 4;

    #pragma unroll
    for (int v = 0; v < 4; v++) {
        const int idx = tid + v*256;
        const int r   = idx >> 4;
        const int c4  = (idx & 15) << 2;
        *(float4*)&Qs[r][c4] = *(const float4*)&Qp[(size_t)(q0 + r)*DKH + c4];
    }

    float O[4][4];
    float m[4], l[4];
    #pragma unroll
    for (int i = 0; i < 4; i++) {
        m[i] = -1e30f; l[i] = 0.f;
        O[i][0] = O[i][1] = O[i][2] = O[i][3] = 0.f;
    }

    for (int kt = 0; kt < SS; kt += 32) {
        __syncthreads();
        #pragma unroll
        for (int v = 0; v < 2; v++) {
            const int idx = tid + v*256;
            const int r   = idx >> 4;
            const int c4  = (idx & 15) << 2;
            *(float4*)&Ks[r][c4] = *(const float4*)&Kp[(size_t)(kt + r)*DKH + c4];
            *(float4*)&Vs[r][c4] = *(const float4*)&Vp[(size_t)(kt + r)*DKH + c4];
        }
        if (tid < 32) msk[tid] = mask[b*SS + kt + tid];
        __syncthreads();

        float sv[4][2];
        #pragma unroll
        for (int i = 0; i < 4; i++) { sv[i][0] = 0.f; sv[i][1] = 0.f; }

        #pragma unroll
        for (int d4 = 0; d4 < 64; d4 += 4) {
            float4 k0v = *(const float4*)&Ks[tx][d4];
            float4 k1v = *(const float4*)&Ks[tx+16][d4];
            #pragma unroll
            for (int i = 0; i < 4; i++) {
                float4 qv = *(const float4*)&Qs[ty + 16*i][d4];
                sv[i][0] += qv.x*k0v.x + qv.y*k0v.y + qv.z*k0v.z + qv.w*k0v.w;
                sv[i][1] += qv.x*k1v.x + qv.y*k1v.y + qv.z*k1v.z + qv.w*k1v.w;
            }
        }
        __syncthreads();

        const int kk0 = tx, kk1 = tx + 16;
        const int m0v = msk[kk0], m1v = msk[kk1];
        #pragma unroll
        for (int i = 0; i < 4; i++) {
            float s0 = sv[i][0] * 0.125f;
            float s1 = sv[i][1] * 0.125f;
            if (m0v == 0) s0 = -1e30f;
            if (m1v == 0) s1 = -1e30f;
            float tm = fmaxf(s0, s1);
            #pragma unroll
            for (int o = 8; o; o >>= 1)
                tm = fmaxf(tm, __shfl_xor_sync(0xffffffffu, tm, o));
            const float mn  = fmaxf(m[i], tm);
            const float fac = (m[i] < -1e29f) ? 0.f : __expf(m[i] - mn);
            const float p0  = (s0 < -1e29f) ? 0.f : __expf(s0 - mn);
            const float p1  = (s1 < -1e29f) ? 0.f : __expf(s1 - mn);
            float rs = p0 + p1;
            #pragma unroll
            for (int o = 8; o; o >>= 1)
                rs += __shfl_xor_sync(0xffffffffu, rs, o);
            l[i] = l[i]*fac + rs;
            m[i] = mn;
            O[i][0] *= fac; O[i][1] *= fac; O[i][2] *= fac; O[i][3] *= fac;
            Ps[ty + 16*i][kk0] = p0;
            Ps[ty + 16*i][kk1] = p1;
        }
        __syncthreads();

        #pragma unroll 4
        for (int k = 0; k < 32; k++) {
            float4 vv = *(const float4*)&Vs[k][tx*4];
            #pragma unroll
            for (int i = 0; i < 4; i++) {
                const float p = Ps[ty + 16*i][k];
                O[i][0] += p * vv.x;
                O[i][1] += p * vv.y;
                O[i][2] += p * vv.z;
                O[i][3] += p * vv.w;
            }
        }
    }

    #pragma unroll
    for (int i = 0; i < 4; i++) {
        const int q   = q0 + ty + 16*i;
        const float inv = (l[i] > 0.f) ? (1.0f / l[i]) : 0.f;
        float4 ov = make_float4(O[i][0]*inv, O[i][1]*inv, O[i][2]*inv, O[i][3]*inv);
        *(float4*)&g_Y[((size_t)b*SS + q)*DM + h*DKH + tx*4] = ov;
    }
}

// ---------------------------------------------------------------------------
extern "C" void kernel_launch(void* const* d_in, const int* in_sizes, int n_in,
                              void* d_out, int out_size)
{
    const float* x    = (const float*)d_in[0];
    const int*   mask = (const int*)  d_in[1];
    const float* Wq   = (const float*)d_in[2];
    const float* Wk   = (const float*)d_in[3];
    const float* Wv   = (const float*)d_in[4];
    const float* Wo   = (const float*)d_in[5];
    float*       out  = (float*)d_out;

    qkv_mma<<<dim3(DM/128, MR/128, 3), 256>>>(x, Wq, Wk, Wv);
    attn_kernel<<<dim3(SS/64, NH, BB), 256>>>(mask);
    outproj_mma<<<dim3(DM/128, MR/128, 1), 256>>>(Wo, out);
}